// round 11
// baseline (speedup 1.0000x reference)
#include <cuda_runtime.h>
#include <cuda_bf16.h>
#include <math.h>
#include <stdint.h>

#define BSZn   2
#define SEQn   512
#define DMODEL 768
#define DINNER 1536
#define NHEADSn 24
#define HEADDIMn 64
#define DSTATEn 64
#define CONVDIM 1664
#define DIP    3224
#define BT     (BSZn*SEQn)   // 1024
#define DFF    3072
#define EPSV   1e-5f
#define NCH    8
#define CHS    (SEQn/NCH)    // 64
#define NG96   (2*BSZn*NHEADSn)  // 96

typedef __nv_bfloat16 bf16;

// ---------------- scratch ----------------
__device__ float g_zx  [BT*DIP];
__device__ float g_xbcf[BT*CONVDIM];
__device__ float g_xbcb[BT*CONVDIM];
__device__ float g_dtp [BT*NHEADSn];
__device__ float g_dAe [BT*NHEADSn];
__device__ float g_yf  [BT*DINNER];
__device__ float g_yb  [BT*DINNER];
__device__ float g_mi  [BT*DMODEL];
__device__ float g_apre[NG96*SEQn];
__device__ __align__(16) float g_hend[NG96*NCH*4096];
__device__ __align__(16) float g_Hc  [NG96*NCH*4096];
__device__ __align__(16) bf16 g_xnh [BT*DMODEL],  g_xnl [BT*DMODEL];
__device__ __align__(16) bf16 g_ysh [BT*DINNER],  g_ysl [BT*DINNER];
__device__ __align__(16) bf16 g_mh  [BT*DMODEL],  g_ml  [BT*DMODEL];
__device__ __align__(16) bf16 g_h1h [BT*DFF],     g_h1l [BT*DFF];
__device__ __align__(16) bf16 g_wip_h[DIP*DMODEL],   g_wip_l[DIP*DMODEL];
__device__ __align__(16) bf16 g_wop_h[DMODEL*DINNER], g_wop_l[DMODEL*DINNER];
__device__ __align__(16) bf16 g_w1_h [DFF*DMODEL],   g_w1_l [DFF*DMODEL];
__device__ __align__(16) bf16 g_w2_h [DMODEL*DFF],   g_w2_l [DMODEL*DFF];

// ---------------- helpers ----------------
__device__ __forceinline__ float warp_sum(float v) {
    #pragma unroll
    for (int o = 16; o > 0; o >>= 1) v += __shfl_xor_sync(0xffffffffu, v, o);
    return v;
}
__device__ __forceinline__ float siluf(float x) { return x / (1.f + expf(-x)); }
__device__ __forceinline__ float geluf(float x) { return 0.5f * x * (1.f + erff(x * 0.70710678118654752f)); }

__device__ __forceinline__ uint32_t smem_u32(const void* p) {
    uint32_t a;
    asm("{ .reg .u64 t; cvta.to.shared.u64 t, %1; cvt.u32.u64 %0, t; }" : "=r"(a) : "l"(p));
    return a;
}
__device__ __forceinline__ void mma_bf16(float* c, const uint32_t* a, const uint32_t* b) {
    asm volatile(
        "mma.sync.aligned.m16n8k16.row.col.f32.bf16.bf16.f32 "
        "{%0,%1,%2,%3},{%4,%5,%6,%7},{%8,%9},{%0,%1,%2,%3};"
        : "+f"(c[0]), "+f"(c[1]), "+f"(c[2]), "+f"(c[3])
        : "r"(a[0]), "r"(a[1]), "r"(a[2]), "r"(a[3]), "r"(b[0]), "r"(b[1]));
}
__device__ __forceinline__ void ldsm4(uint32_t* r, uint32_t addr) {
    asm volatile("ldmatrix.sync.aligned.m8n8.x4.shared.b16 {%0,%1,%2,%3}, [%4];"
                 : "=r"(r[0]), "=r"(r[1]), "=r"(r[2]), "=r"(r[3]) : "r"(addr));
}
__device__ __forceinline__ void cpasync16(uint32_t dst, const void* src, uint32_t ssz) {
    asm volatile("cp.async.cg.shared.global [%0], [%1], 16, %2;"
                 :: "r"(dst), "l"(src), "r"(ssz) : "memory");
}
__device__ __forceinline__ void cp_commit() {
    asm volatile("cp.async.commit_group;" ::: "memory");
}
template<int Np>
__device__ __forceinline__ void cp_wait() {
    asm volatile("cp.async.wait_group %0;" :: "n"(Np) : "memory");
}
__device__ __forceinline__ void split1(float x, bf16& h, bf16& l) {
    h = __float2bfloat16_rn(x);
    l = __float2bfloat16_rn(x - __bfloat162float(h));
}

// ---------------- weight hi/lo split ----------------
__global__ void wsplit_kernel(const float* __restrict__ w, bf16* __restrict__ wh,
                              bf16* __restrict__ wl, int n4) {
    int i = blockIdx.x * blockDim.x + threadIdx.x;
    if (i >= n4) return;
    float4 v = reinterpret_cast<const float4*>(w)[i];
    bf16 h0, h1, h2, h3, l0, l1, l2, l3;
    split1(v.x, h0, l0); split1(v.y, h1, l1);
    split1(v.z, h2, l2); split1(v.w, h3, l3);
    __nv_bfloat162 hp0; hp0.x = h0; hp0.y = h1;
    __nv_bfloat162 hp1; hp1.x = h2; hp1.y = h3;
    __nv_bfloat162 lp0; lp0.x = l0; lp0.y = l1;
    __nv_bfloat162 lp1; lp1.x = l2; lp1.y = l3;
    uint2 hh = make_uint2(*reinterpret_cast<uint32_t*>(&hp0), *reinterpret_cast<uint32_t*>(&hp1));
    uint2 ll = make_uint2(*reinterpret_cast<uint32_t*>(&lp0), *reinterpret_cast<uint32_t*>(&lp1));
    reinterpret_cast<uint2*>(wh)[i] = hh;
    reinterpret_cast<uint2*>(wl)[i] = ll;
}

// ---------------- LayerNorm -> bf16 hi/lo planes ----------------
__global__ void ln_hl_kernel(const float* __restrict__ in, const float* __restrict__ w,
                             const float* __restrict__ b,
                             bf16* __restrict__ oh, bf16* __restrict__ ol) {
    int row = blockIdx.x;
    int tid = threadIdx.x;
    const float* x = in + (long)row * DMODEL;
    float v[3], s = 0.f, ss = 0.f;
    #pragma unroll
    for (int i = 0; i < 3; i++) {
        v[i] = x[tid + i * 256];
        s += v[i]; ss += v[i] * v[i];
    }
    __shared__ float sr[8], sr2[8], bres[2];
    float ws = warp_sum(s), ws2 = warp_sum(ss);
    int lane = tid & 31, wid = tid >> 5;
    if (lane == 0) { sr[wid] = ws; sr2[wid] = ws2; }
    __syncthreads();
    if (tid == 0) {
        float a = 0.f, c = 0.f;
        #pragma unroll
        for (int i = 0; i < 8; i++) { a += sr[i]; c += sr2[i]; }
        bres[0] = a; bres[1] = c;
    }
    __syncthreads();
    float mu  = bres[0] * (1.f / DMODEL);
    float var = bres[1] * (1.f / DMODEL) - mu * mu;
    float r = rsqrtf(var + EPSV);
    #pragma unroll
    for (int i = 0; i < 3; i++) {
        int c = tid + i * 256;
        float o = (v[i] - mu) * r * w[c] + b[c];
        bf16 h, l; split1(o, h, l);
        oh[(long)row * DMODEL + c] = h;
        ol[(long)row * DMODEL + c] = l;
    }
}

// ======= GEMM (pre-split bf16 hi/lo, cp.async x3, ldmatrix, HMMA 3-product) ==
#define RS 80
#define A_PL (128 * RS)
#define B_PL (64 * RS)
#define STG  (2 * A_PL + 2 * B_PL)
#define GEMM_SMEM (3 * STG)

template<int EPI, int OUTHL>
__global__ void __launch_bounds__(256, 2) gemm_bf16p(
        const bf16* __restrict__ Ah_, const bf16* __restrict__ Al_,
        const bf16* __restrict__ Wh_, const bf16* __restrict__ Wl_,
        const float* __restrict__ bias, const float* __restrict__ resid,
        float* __restrict__ C, bf16* __restrict__ Ch, bf16* __restrict__ Cl,
        int M, int N, int K) {
    extern __shared__ char smem[];
    uint32_t sb = smem_u32(smem);
    const int tid = threadIdx.x;
    const int lane = tid & 31, wid = tid >> 5;
    const int warpM = wid & 3, warpN = wid >> 2;
    const int row0 = blockIdx.y * 128;
    const int col0 = blockIdx.x * 64;
    const int quad = lane >> 3, r8 = lane & 7;
    const int g = lane >> 2, tg = lane & 3;

    float acc[2][4][4];
    #pragma unroll
    for (int mt = 0; mt < 2; mt++)
        #pragma unroll
        for (int nt = 0; nt < 4; nt++)
            #pragma unroll
            for (int i = 0; i < 4; i++) acc[mt][nt][i] = 0.f;

    const int ar0 = tid >> 2,          ac0 = tid & 3;
    const int ar1 = (tid + 256) >> 2,  ac1 = ac0;
    const int br  = tid >> 2,          bc  = tid & 3;
    const int bn  = col0 + br;
    const int bnc = bn < N ? bn : (N - 1);
    const uint32_t bsz = bn < N ? 16u : 0u;

    auto issue = [&](int kt, int st) {
        uint32_t base = sb + st * STG;
        int k0 = kt * 32;
        cpasync16(base + ar0 * RS + ac0 * 16,        &Ah_[(long)(row0 + ar0) * K + k0 + ac0 * 8], 16);
        cpasync16(base + A_PL + ar0 * RS + ac0 * 16, &Al_[(long)(row0 + ar0) * K + k0 + ac0 * 8], 16);
        cpasync16(base + ar1 * RS + ac1 * 16,        &Ah_[(long)(row0 + ar1) * K + k0 + ac1 * 8], 16);
        cpasync16(base + A_PL + ar1 * RS + ac1 * 16, &Al_[(long)(row0 + ar1) * K + k0 + ac1 * 8], 16);
        cpasync16(base + 2 * A_PL + br * RS + bc * 16,        &Wh_[(long)bnc * K + k0 + bc * 8], bsz);
        cpasync16(base + 2 * A_PL + B_PL + br * RS + bc * 16, &Wl_[(long)bnc * K + k0 + bc * 8], bsz);
        cp_commit();
    };

    const int ntiles = K / 32;
    issue(0, 0);
    issue(1, 1);

    for (int kt = 0; kt < ntiles; kt++) {
        cp_wait<1>();
        __syncthreads();
        if (kt + 2 < ntiles) issue(kt + 2, (kt + 2) % 3);
        else cp_commit();

        uint32_t base = sb + (kt % 3) * STG;
        uint32_t pAh = base, pAl = base + A_PL;
        uint32_t pBh = base + 2 * A_PL, pBl = pBh + B_PL;

        uint32_t ah[2][2][4], al[2][2][4], bh[2][2][4], bl[2][2][4];
        {
            uint32_t kbA = (quad >> 1) * 16;
            uint32_t kbB = (quad & 1) * 16;
            #pragma unroll
            for (int mt = 0; mt < 2; mt++) {
                uint32_t ra = (uint32_t)((warpM * 32 + mt * 16 + (quad & 1) * 8 + r8) * RS) + kbA;
                ldsm4(ah[0][mt], pAh + ra);
                ldsm4(al[0][mt], pAl + ra);
            }
            #pragma unroll
            for (int nt = 0; nt < 2; nt++) {
                uint32_t rb = (uint32_t)((warpN * 32 + nt * 16 + (quad >> 1) * 8 + r8) * RS) + kbB;
                ldsm4(bh[0][nt], pBh + rb);
                ldsm4(bl[0][nt], pBl + rb);
            }
        }
        #pragma unroll
        for (int slab = 0; slab < 2; slab++) {
            if (slab == 0) {
                uint32_t kbA = 32 + (quad >> 1) * 16;
                uint32_t kbB = 32 + (quad & 1) * 16;
                #pragma unroll
                for (int mt = 0; mt < 2; mt++) {
                    uint32_t ra = (uint32_t)((warpM * 32 + mt * 16 + (quad & 1) * 8 + r8) * RS) + kbA;
                    ldsm4(ah[1][mt], pAh + ra);
                    ldsm4(al[1][mt], pAl + ra);
                }
                #pragma unroll
                for (int nt = 0; nt < 2; nt++) {
                    uint32_t rb = (uint32_t)((warpN * 32 + nt * 16 + (quad >> 1) * 8 + r8) * RS) + kbB;
                    ldsm4(bh[1][nt], pBh + rb);
                    ldsm4(bl[1][nt], pBl + rb);
                }
            }
            #pragma unroll
            for (int mt = 0; mt < 2; mt++)
                #pragma unroll
                for (int nt16 = 0; nt16 < 2; nt16++) {
                    mma_bf16(acc[mt][nt16 * 2 + 0], ah[slab][mt], &bl[slab][nt16][0]);
                    mma_bf16(acc[mt][nt16 * 2 + 0], al[slab][mt], &bh[slab][nt16][0]);
                    mma_bf16(acc[mt][nt16 * 2 + 0], ah[slab][mt], &bh[slab][nt16][0]);
                    mma_bf16(acc[mt][nt16 * 2 + 1], ah[slab][mt], &bl[slab][nt16][2]);
                    mma_bf16(acc[mt][nt16 * 2 + 1], al[slab][mt], &bh[slab][nt16][2]);
                    mma_bf16(acc[mt][nt16 * 2 + 1], ah[slab][mt], &bh[slab][nt16][2]);
                }
        }
    }

    #pragma unroll
    for (int mt = 0; mt < 2; mt++) {
        int rbase = row0 + warpM * 32 + mt * 16 + g;
        #pragma unroll
        for (int nt = 0; nt < 4; nt++) {
            int col = col0 + warpN * 32 + nt * 8 + tg * 2;
            if (col < N) {
                float2 v0 = make_float2(acc[mt][nt][0], acc[mt][nt][1]);
                float2 v1 = make_float2(acc[mt][nt][2], acc[mt][nt][3]);
                if (EPI == 1) {
                    float b0 = bias[col], b1 = bias[col + 1];
                    v0.x = geluf(v0.x + b0); v0.y = geluf(v0.y + b1);
                    v1.x = geluf(v1.x + b0); v1.y = geluf(v1.y + b1);
                }
                if (EPI == 2) {
                    float b0 = bias[col], b1 = bias[col + 1];
                    float2 r0 = *reinterpret_cast<const float2*>(&resid[(long)rbase * N + col]);
                    float2 r1 = *reinterpret_cast<const float2*>(&resid[(long)(rbase + 8) * N + col]);
                    v0.x += b0 + r0.x; v0.y += b1 + r0.y;
                    v1.x += b0 + r1.x; v1.y += b1 + r1.y;
                }
                if (OUTHL) {
                    bf16 h0, h1, l0, l1;
                    split1(v0.x, h0, l0); split1(v0.y, h1, l1);
                    __nv_bfloat162 hp; hp.x = h0; hp.y = h1;
                    __nv_bfloat162 lp; lp.x = l0; lp.y = l1;
                    *reinterpret_cast<uint32_t*>(&Ch[(long)rbase * N + col]) = *reinterpret_cast<uint32_t*>(&hp);
                    *reinterpret_cast<uint32_t*>(&Cl[(long)rbase * N + col]) = *reinterpret_cast<uint32_t*>(&lp);
                    split1(v1.x, h0, l0); split1(v1.y, h1, l1);
                    hp.x = h0; hp.y = h1; lp.x = l0; lp.y = l1;
                    *reinterpret_cast<uint32_t*>(&Ch[(long)(rbase + 8) * N + col]) = *reinterpret_cast<uint32_t*>(&hp);
                    *reinterpret_cast<uint32_t*>(&Cl[(long)(rbase + 8) * N + col]) = *reinterpret_cast<uint32_t*>(&lp);
                } else {
                    *reinterpret_cast<float2*>(&C[(long)rbase * N + col])       = v0;
                    *reinterpret_cast<float2*>(&C[(long)(rbase + 8) * N + col]) = v1;
                }
            }
        }
    }
}

// ---------------- depthwise conv (causal fwd + anti-causal bwd) + SiLU --------
__global__ void conv_kernel(const float* __restrict__ zx, const float* __restrict__ cw,
                            const float* __restrict__ cb,
                            float* __restrict__ xf, float* __restrict__ xb) {
    long idx = (long)blockIdx.x * blockDim.x + threadIdx.x;
    if (idx >= (long)BT * CONVDIM) return;
    int c = (int)(idx % CONVDIM);
    long bt = idx / CONVDIM;
    int t = (int)(bt % SEQn);
    int b = (int)(bt / SEQn);
    float w0 = cw[c*4+0], w1 = cw[c*4+1], w2 = cw[c*4+2], w3 = cw[c*4+3];
    float bias = cb[c];
    const float* base = zx + ((long)b * SEQn) * DIP + DINNER + c;
    float af = bias;
    if (t >= 3) af += w0 * base[(long)(t-3) * DIP];
    if (t >= 2) af += w1 * base[(long)(t-2) * DIP];
    if (t >= 1) af += w2 * base[(long)(t-1) * DIP];
    af += w3 * base[(long)t * DIP];
    xf[idx] = siluf(af);
    float ab = bias;
    if (t + 3 < SEQn) ab += w0 * base[(long)(t+3) * DIP];
    if (t + 2 < SEQn) ab += w1 * base[(long)(t+2) * DIP];
    if (t + 1 < SEQn) ab += w2 * base[(long)(t+1) * DIP];
    ab += w3 * base[(long)t * DIP];
    xb[idx] = siluf(ab);
}

// ---------------- dt processing ----------------
__global__ void dt_kernel(const float* __restrict__ zx, const float* __restrict__ dt_bias,
                          const float* __restrict__ A_log,
                          float* __restrict__ dtp, float* __restrict__ dAe) {
    int idx = blockIdx.x * blockDim.x + threadIdx.x;
    if (idx >= BT * NHEADSn) return;
    int h = idx % NHEADSn;
    long row = idx / NHEADSn;
    float d = zx[row * DIP + DINNER + CONVDIM + h] + dt_bias[h];
    float sp = (d > 20.f) ? d : log1pf(expf(d));
    dtp[idx] = sp;
    dAe[idx] = expf(-expf(A_log[h]) * sp);
}

// --------- apre: within-chunk prefix products of dA (scan order) -------------
__global__ void apre_kernel(const float* __restrict__ dAe, float* __restrict__ apre) {
    int gid = blockIdx.x * blockDim.x + threadIdx.x;
    if (gid >= NG96 * NCH) return;
    int c = gid % NCH;
    int r96 = gid / NCH;
    int hh = r96 % NHEADSn;
    int rb = r96 / NHEADSn;
    int b = rb % BSZn, dir = rb / BSZn;
    float a = 1.f;
    for (int sl = 0; sl < CHS; sl++) {
        int s = c * CHS + sl;
        int t = dir ? (SEQn - 1 - s) : s;
        a *= dAe[((long)b * SEQn + t) * NHEADSn + hh];
        apre[(long)r96 * SEQn + s] = a;
    }
}

// --------- chunked local scan: 768 blocks, no smem, no barriers --------------
// blk = r96*NCH + c.  Thread (p=tid>>2, q=tid&3) owns states n in [16q,16q+16).
__global__ void __launch_bounds__(256, 2) chunk_scan(
        const float* __restrict__ xbcf, const float* __restrict__ xbcb,
        const float* __restrict__ dtp, const float* __restrict__ dAe,
        const float* __restrict__ Dp_,
        float* __restrict__ yf, float* __restrict__ yb,
        float* __restrict__ hend) {
    int blk = blockIdx.x;
    int c = blk % NCH;
    int r96 = blk / NCH;
    int hh = r96 % NHEADSn;
    int rb = r96 / NHEADSn;
    int b = rb % BSZn, dir = rb / BSZn;
    const float* xbc = dir ? xbcb : xbcf;
    float* y = dir ? yb : yf;
    int tid = threadIdx.x;
    int p = tid >> 2, q = tid & 3;
    float Dv = Dp_[hh];
    long rowbase = (long)b * SEQn;

    float hst[16];
    #pragma unroll
    for (int j = 0; j < 16; j++) hst[j] = 0.f;

    float bv[2][16], cv[2][16], xx[2], dtv[2], dav[2];
    long rowreg[2];

    auto loadstep = [&](int s, int buf) {
        int t = dir ? (SEQn - 1 - s) : s;
        long row = rowbase + t;
        rowreg[buf] = row;
        const float* base = &xbc[row * CONVDIM];
        const float4* pb = reinterpret_cast<const float4*>(base + DINNER + q * 16);
        const float4* pc = reinterpret_cast<const float4*>(base + DINNER + DSTATEn + q * 16);
        *reinterpret_cast<float4*>(&bv[buf][0])  = pb[0];
        *reinterpret_cast<float4*>(&bv[buf][4])  = pb[1];
        *reinterpret_cast<float4*>(&bv[buf][8])  = pb[2];
        *reinterpret_cast<float4*>(&bv[buf][12]) = pb[3];
        *reinterpret_cast<float4*>(&cv[buf][0])  = pc[0];
        *reinterpret_cast<float4*>(&cv[buf][4])  = pc[1];
        *reinterpret_cast<float4*>(&cv[buf][8])  = pc[2];
        *reinterpret_cast<float4*>(&cv[buf][12]) = pc[3];
        xx[buf]  = base[hh * HEADDIMn + p];
        dtv[buf] = dtp[row * NHEADSn + hh];
        dav[buf] = dAe[row * NHEADSn + hh];
    };

    int s0 = c * CHS;
    loadstep(s0, 0);
    for (int i = 0; i < CHS; i++) {
        int cur = i & 1, nxt = cur ^ 1;
        if (i + 1 < CHS) loadstep(s0 + i + 1, nxt);
        float cdt = dtv[cur], cdA = dav[cur], cx = xx[cur];
        float c1 = cdt * cx;
        float yv0 = (q == 0) ? Dv * cx : 0.f;
        float yv1 = 0.f, yv2 = 0.f, yv3 = 0.f;
        #pragma unroll
        for (int j = 0; j < 16; j += 4) {
            hst[j]     = cdA * hst[j]     + c1 * bv[cur][j];     yv0 += hst[j]     * cv[cur][j];
            hst[j + 1] = cdA * hst[j + 1] + c1 * bv[cur][j + 1]; yv1 += hst[j + 1] * cv[cur][j + 1];
            hst[j + 2] = cdA * hst[j + 2] + c1 * bv[cur][j + 2]; yv2 += hst[j + 2] * cv[cur][j + 2];
            hst[j + 3] = cdA * hst[j + 3] + c1 * bv[cur][j + 3]; yv3 += hst[j + 3] * cv[cur][j + 3];
        }
        float yv = (yv0 + yv1) + (yv2 + yv3);
        yv += __shfl_xor_sync(0xffffffffu, yv, 1);
        yv += __shfl_xor_sync(0xffffffffu, yv, 2);
        if (q == 0) y[rowreg[cur] * DINNER + hh * HEADDIMn + p] = yv;
    }
    // write local chunk-end state
    float4* he = reinterpret_cast<float4*>(&hend[(long)blk * 4096 + p * 64 + q * 16]);
    he[0] = *reinterpret_cast<float4*>(&hst[0]);
    he[1] = *reinterpret_cast<float4*>(&hst[4]);
    he[2] = *reinterpret_cast<float4*>(&hst[8]);
    he[3] = *reinterpret_cast<float4*>(&hst[12]);
}

// --------- combine: H_{c+1} = P_c * H_c + hend_c ; store carries -------------
__global__ void combine_kernel(const float* __restrict__ hend, const float* __restrict__ apre,
                               float* __restrict__ Hc) {
    int r96 = blockIdx.x;
    int tid = threadIdx.x;
    int p = tid >> 2, q = tid & 3;
    int eo = p * 64 + q * 16;
    float H[16];
    #pragma unroll
    for (int j = 0; j < 16; j++) H[j] = 0.f;
    for (int c = 0; c < NCH; c++) {
        if (c > 0) {
            float4* dst = reinterpret_cast<float4*>(&Hc[((long)r96 * NCH + c) * 4096 + eo]);
            dst[0] = *reinterpret_cast<float4*>(&H[0]);
            dst[1] = *reinterpret_cast<float4*>(&H[4]);
            dst[2] = *reinterpret_cast<float4*>(&H[8]);
            dst[3] = *reinterpret_cast<float4*>(&H[12]);
        }
        float Pc = apre[(long)r96 * SEQn + c * CHS + CHS - 1];
        const float4* he = reinterpret_cast<const float4*>(&hend[((long)r96 * NCH + c) * 4096 + eo]);
        float hv[16];
        *reinterpret_cast<float4*>(&hv[0])  = he[0];
        *reinterpret_cast<float4*>(&hv[4])  = he[1];
        *reinterpret_cast<float4*>(&hv[8])  = he[2];
        *reinterpret_cast<float4*>(&hv[12]) = he[3];
        #pragma unroll
        for (int j = 0; j < 16; j++) H[j] = Pc * H[j] + hv[j];
    }
}

// --------- correction: y[s] += a_s * (C_s · H_c) for chunks c>=1 -------------
__global__ void corr_kernel(const float* __restrict__ xbcf, const float* __restrict__ xbcb,
                            const float* __restrict__ apre, const float* __restrict__ Hc,
                            float* __restrict__ yf, float* __restrict__ yb) {
    int blk = blockIdx.x;                  // r96*(NCH-1) + (c-1)
    int c = blk % (NCH - 1) + 1;
    int r96 = blk / (NCH - 1);
    int hh = r96 % NHEADSn;
    int rb = r96 / NHEADSn;
    int b = rb % BSZn, dir = rb / BSZn;
    const float* xbc = dir ? xbcb : xbcf;
    float* y = dir ? yb : yf;
    int tid = threadIdx.x;
    int p = tid >> 2, q = tid & 3;
    long rowbase = (long)b * SEQn;

    float H[16];
    const float4* hp = reinterpret_cast<const float4*>(&Hc[((long)r96 * NCH + c) * 4096 + p * 64 + q * 16]);
    *reinterpret_cast<float4*>(&H[0])  = hp[0];
    *reinterpret_cast<float4*>(&H[4])  = hp[1];
    *reinterpret_cast<float4*>(&H[8])  = hp[2];
    *reinterpret_cast<float4*>(&H[12]) = hp[3];

    for (int sl = 0; sl < CHS; sl++) {
        int s = c * CHS + sl;
        int t = dir ? (SEQn - 1 - s) : s;
        long row = rowbase + t;
        const float4* pc = reinterpret_cast<const float4*>(&xbc[row * CONVDIM + DINNER + DSTATEn + q * 16]);
        float cvv[16];
        *reinterpret_cast<float4*>(&cvv[0])  = pc[0];
        *reinterpret_cast<float4*>(&cvv[4])  = pc[1];
        *reinterpret_cast<float4*>(&cvv[8])  = pc[2];
        *reinterpret_cast<float4*>(&cvv[12]) = pc[3];
        float a = apre[(long)r96 * SEQn + s];
        float t0 = 0.f, t1 = 0.f, t2 = 0.f, t3 = 0.f;
        #pragma unroll
        for (int j = 0; j < 16; j += 4) {
            t0 += H[j]     * cvv[j];
            t1 += H[j + 1] * cvv[j + 1];
            t2 += H[j + 2] * cvv[j + 2];
            t3 += H[j + 3] * cvv[j + 3];
        }
        float tot = (t0 + t1) + (t2 + t3);
        tot += __shfl_xor_sync(0xffffffffu, tot, 1);
        tot += __shfl_xor_sync(0xffffffffu, tot, 2);
        if (q == 0) y[row * DINNER + hh * HEADDIMn + p] += a * tot;
    }
}

// ------ gate + RMSNorm + sum -> bf16 hi/lo planes ----------------
__global__ void gatenorm_kernel(const float* __restrict__ yf, const float* __restrict__ yb,
                                const float* __restrict__ zx, const float* __restrict__ nw,
                                bf16* __restrict__ oh, bf16* __restrict__ ol) {
    int row = blockIdx.x;
    int tid = threadIdx.x;
    const float* z = zx + (long)row * DIP;
    float gf[6], gb[6], ssf = 0.f, ssb = 0.f;
    #pragma unroll
    for (int i = 0; i < 6; i++) {
        int c = tid + i * 256;
        float s = siluf(z[c]);
        float a = yf[(long)row * DINNER + c] * s;
        float d = yb[(long)row * DINNER + c] * s;
        gf[i] = a; gb[i] = d;
        ssf += a * a; ssb += d * d;
    }
    __shared__ float r1[8], r2[8], bres[2];
    float w1 = warp_sum(ssf), w2 = warp_sum(ssb);
    int lane = tid & 31, wid = tid >> 5;
    if (lane == 0) { r1[wid] = w1; r2[wid] = w2; }
    __syncthreads();
    if (tid == 0) {
        float a = 0.f, c = 0.f;
        #pragma unroll
        for (int i = 0; i < 8; i++) { a += r1[i]; c += r2[i]; }
        bres[0] = a; bres[1] = c;
    }
    __syncthreads();
    float rf = rsqrtf(bres[0] * (1.f / DINNER) + EPSV);
    float rb = rsqrtf(bres[1] * (1.f / DINNER) + EPSV);
    #pragma unroll
    for (int i = 0; i < 6; i++) {
        int c = tid + i * 256;
        float o = (gf[i] * rf + gb[i] * rb) * nw[c];
        bf16 h, l; split1(o, h, l);
        oh[(long)row * DINNER + c] = h;
        ol[(long)row * DINNER + c] = l;
    }
}

// ---------------- launch ----------------
extern "C" void kernel_launch(void* const* d_in, const int* in_sizes, int n_in,
                              void* d_out, int out_size) {
    const float* x        = (const float*)d_in[0];
    const float* in_proj  = (const float*)d_in[1];
    const float* conv_w   = (const float*)d_in[2];
    const float* conv_b   = (const float*)d_in[3];
    const float* dt_bias  = (const float*)d_in[4];
    const float* A_log    = (const float*)d_in[5];
    const float* D_param  = (const float*)d_in[6];
    const float* norm_w   = (const float*)d_in[7];
    const float* out_proj = (const float*)d_in[8];
    const float* ln1_w    = (const float*)d_in[9];
    const float* ln1_b    = (const float*)d_in[10];
    const float* ln2_w    = (const float*)d_in[11];
    const float* ln2_b    = (const float*)d_in[12];
    const float* ff_w1    = (const float*)d_in[13];
    const float* ff_b1    = (const float*)d_in[14];
    const float* ff_w2    = (const float*)d_in[15];
    const float* ff_b2    = (const float*)d_in[16];
    float* out = (float*)d_out;

    float *p_zx, *p_xbcf, *p_xbcb, *p_dtp, *p_dAe, *p_yf, *p_yb, *p_mi;
    float *p_apre, *p_hend, *p_Hc;
    bf16 *p_xnh, *p_xnl, *p_ysh, *p_ysl, *p_mh, *p_ml, *p_h1h, *p_h1l;
    bf16 *p_wip_h, *p_wip_l, *p_wop_h, *p_wop_l, *p_w1_h, *p_w1_l, *p_w2_h, *p_w2_l;
    cudaGetSymbolAddress((void**)&p_zx,   g_zx);
    cudaGetSymbolAddress((void**)&p_xbcf, g_xbcf);
    cudaGetSymbolAddress((void**)&p_xbcb, g_xbcb);
    cudaGetSymbolAddress((void**)&p_dtp,  g_dtp);
    cudaGetSymbolAddress((void**)&p_dAe,  g_dAe);
    cudaGetSymbolAddress((void**)&p_yf,   g_yf);
    cudaGetSymbolAddress((void**)&p_yb,   g_yb);
    cudaGetSymbolAddress((void**)&p_mi,   g_mi);
    cudaGetSymbolAddress((void**)&p_apre, g_apre);
    cudaGetSymbolAddress((void**)&p_hend, g_hend);
    cudaGetSymbolAddress((void**)&p_Hc,   g_Hc);
    cudaGetSymbolAddress((void**)&p_xnh,  g_xnh);
    cudaGetSymbolAddress((void**)&p_xnl,  g_xnl);
    cudaGetSymbolAddress((void**)&p_ysh,  g_ysh);
    cudaGetSymbolAddress((void**)&p_ysl,  g_ysl);
    cudaGetSymbolAddress((void**)&p_mh,   g_mh);
    cudaGetSymbolAddress((void**)&p_ml,   g_ml);
    cudaGetSymbolAddress((void**)&p_h1h,  g_h1h);
    cudaGetSymbolAddress((void**)&p_h1l,  g_h1l);
    cudaGetSymbolAddress((void**)&p_wip_h, g_wip_h);
    cudaGetSymbolAddress((void**)&p_wip_l, g_wip_l);
    cudaGetSymbolAddress((void**)&p_wop_h, g_wop_h);
    cudaGetSymbolAddress((void**)&p_wop_l, g_wop_l);
    cudaGetSymbolAddress((void**)&p_w1_h,  g_w1_h);
    cudaGetSymbolAddress((void**)&p_w1_l,  g_w1_l);
    cudaGetSymbolAddress((void**)&p_w2_h,  g_w2_h);
    cudaGetSymbolAddress((void**)&p_w2_l,  g_w2_l);

    cudaFuncSetAttribute(gemm_bf16p<0,0>, cudaFuncAttributeMaxDynamicSharedMemorySize, GEMM_SMEM);
    cudaFuncSetAttribute(gemm_bf16p<1,1>, cudaFuncAttributeMaxDynamicSharedMemorySize, GEMM_SMEM);
    cudaFuncSetAttribute(gemm_bf16p<2,0>, cudaFuncAttributeMaxDynamicSharedMemorySize, GEMM_SMEM);

    // #0 ln1(x) -> xn planes
    ln_hl_kernel<<<BT, 256>>>(x, ln1_w, ln1_b, p_xnh, p_xnl);
    // #1 split in_proj
    wsplit_kernel<<<(DIP*DMODEL/4 + 255) / 256, 256>>>(in_proj,  p_wip_h, p_wip_l, DIP*DMODEL/4);
    // #2 zxbcdt = xn @ in_proj^T
    gemm_bf16p<0,0><<<dim3((DIP + 63) / 64, BT / 128), 256, GEMM_SMEM>>>(
        p_xnh, p_xnl, p_wip_h, p_wip_l, nullptr, nullptr, p_zx, nullptr, nullptr, BT, DIP, DMODEL);
    // #3 conv + silu (both directions)   <-- ncu capture slot
    {
        long tot = (long)BT * CONVDIM;
        conv_kernel<<<(int)((tot + 255) / 256), 256>>>(p_zx, conv_w, conv_b, p_xbcf, p_xbcb);
    }
    // #4 dt processing
    dt_kernel<<<(BT * NHEADSn + 255) / 256, 256>>>(p_zx, dt_bias, A_log, p_dtp, p_dAe);
    // #5 prefix products
    apre_kernel<<<(NG96 * NCH + 255) / 256, 256>>>(p_dAe, p_apre);
    // #6 chunked local scans
    chunk_scan<<<NG96 * NCH, 256>>>(p_xbcf, p_xbcb, p_dtp, p_dAe, D_param, p_yf, p_yb, p_hend);
    // #7 combine carries
    combine_kernel<<<NG96, 256>>>(p_hend, p_apre, p_Hc);
    // #8 correction
    corr_kernel<<<NG96 * (NCH - 1), 256>>>(p_xbcf, p_xbcb, p_apre, p_Hc, p_yf, p_yb);
    // #9 gate + RMSNorm + sum -> ysum planes
    gatenorm_kernel<<<BT, 256>>>(p_yf, p_yb, p_zx, norm_w, p_ysh, p_ysl);
    // #10 split out_proj
    wsplit_kernel<<<(DMODEL*DINNER/4 + 255) / 256, 256>>>(out_proj, p_wop_h, p_wop_l, DMODEL*DINNER/4);
    // #11 mi = ysum @ out_proj^T
    gemm_bf16p<0,0><<<dim3(DMODEL / 64, BT / 128), 256, GEMM_SMEM>>>(
        p_ysh, p_ysl, p_wop_h, p_wop_l, nullptr, nullptr, p_mi, nullptr, nullptr, BT, DMODEL, DINNER);
    // #12 ln2 -> m planes
    ln_hl_kernel<<<BT, 256>>>(p_mi, ln2_w, ln2_b, p_mh, p_ml);
    // #13 split ff_w1
    wsplit_kernel<<<(DFF*DMODEL/4 + 255) / 256, 256>>>(ff_w1, p_w1_h, p_w1_l, DFF*DMODEL/4);
    // #14 h1 = gelu(m @ ff_w1^T + b1)
    gemm_bf16p<1,1><<<dim3(DFF / 64, BT / 128), 256, GEMM_SMEM>>>(
        p_mh, p_ml, p_w1_h, p_w1_l, ff_b1, nullptr, nullptr, p_h1h, p_h1l, BT, DFF, DMODEL);
    // #15 split ff_w2
    wsplit_kernel<<<(DMODEL*DFF/4 + 255) / 256, 256>>>(ff_w2, p_w2_h, p_w2_l, DMODEL*DFF/4);
    // #16 out = h1 @ ff_w2^T + b2 + x
    gemm_bf16p<2,0><<<dim3(DMODEL / 64, BT / 128), 256, GEMM_SMEM>>>(
        p_h1h, p_h1l, p_w2_h, p_w2_l, ff_b2, x, out, nullptr, nullptr, BT, DMODEL, DFF);
}

// round 12
// speedup vs baseline: 1.4356x; 1.4356x over previous
#include <cuda_runtime.h>
#include <cuda_bf16.h>
#include <math.h>
#include <stdint.h>

#define BSZn   2
#define SEQn   512
#define DMODEL 768
#define DINNER 1536
#define NHEADSn 24
#define HEADDIMn 64
#define DSTATEn 64
#define CONVDIM 1664
#define DIP    3224
#define BT     (BSZn*SEQn)   // 1024
#define DFF    3072
#define EPSV   1e-5f
#define NCH    8
#define CHS    (SEQn/NCH)    // 64
#define NG96   (2*BSZn*NHEADSn)  // 96

typedef __nv_bfloat16 bf16;

// ---------------- scratch ----------------
__device__ float g_zx  [BT*DIP];
__device__ float g_xbcf[BT*CONVDIM];
__device__ float g_xbcb[BT*CONVDIM];
__device__ float g_dtp [BT*NHEADSn];
__device__ float g_dAe [BT*NHEADSn];
__device__ float g_yf  [BT*DINNER];
__device__ float g_yb  [BT*DINNER];
__device__ float g_mi  [BT*DMODEL];
__device__ float g_apre[NG96*SEQn];
__device__ __align__(16) float g_hend[NG96*NCH*4096];
__device__ __align__(16) float g_Hc  [NG96*NCH*4096];
__device__ __align__(16) bf16 g_xnh [BT*DMODEL],  g_xnl [BT*DMODEL];
__device__ __align__(16) bf16 g_ysh [BT*DINNER],  g_ysl [BT*DINNER];
__device__ __align__(16) bf16 g_mh  [BT*DMODEL],  g_ml  [BT*DMODEL];
__device__ __align__(16) bf16 g_h1h [BT*DFF],     g_h1l [BT*DFF];
__device__ __align__(16) bf16 g_wip_h[DIP*DMODEL],   g_wip_l[DIP*DMODEL];
__device__ __align__(16) bf16 g_wop_h[DMODEL*DINNER], g_wop_l[DMODEL*DINNER];
__device__ __align__(16) bf16 g_w1_h [DFF*DMODEL],   g_w1_l [DFF*DMODEL];
__device__ __align__(16) bf16 g_w2_h [DMODEL*DFF],   g_w2_l [DMODEL*DFF];

// ---------------- helpers ----------------
__device__ __forceinline__ float warp_sum(float v) {
    #pragma unroll
    for (int o = 16; o > 0; o >>= 1) v += __shfl_xor_sync(0xffffffffu, v, o);
    return v;
}
__device__ __forceinline__ float siluf(float x) { return x / (1.f + expf(-x)); }
__device__ __forceinline__ float geluf(float x) { return 0.5f * x * (1.f + erff(x * 0.70710678118654752f)); }

__device__ __forceinline__ uint32_t smem_u32(const void* p) {
    uint32_t a;
    asm("{ .reg .u64 t; cvta.to.shared.u64 t, %1; cvt.u32.u64 %0, t; }" : "=r"(a) : "l"(p));
    return a;
}
__device__ __forceinline__ void mma_bf16(float* c, const uint32_t* a, const uint32_t* b) {
    asm volatile(
        "mma.sync.aligned.m16n8k16.row.col.f32.bf16.bf16.f32 "
        "{%0,%1,%2,%3},{%4,%5,%6,%7},{%8,%9},{%0,%1,%2,%3};"
        : "+f"(c[0]), "+f"(c[1]), "+f"(c[2]), "+f"(c[3])
        : "r"(a[0]), "r"(a[1]), "r"(a[2]), "r"(a[3]), "r"(b[0]), "r"(b[1]));
}
__device__ __forceinline__ void ldsm4(uint32_t* r, uint32_t addr) {
    asm volatile("ldmatrix.sync.aligned.m8n8.x4.shared.b16 {%0,%1,%2,%3}, [%4];"
                 : "=r"(r[0]), "=r"(r[1]), "=r"(r[2]), "=r"(r[3]) : "r"(addr));
}
__device__ __forceinline__ void cpasync16(uint32_t dst, const void* src, uint32_t ssz) {
    asm volatile("cp.async.cg.shared.global [%0], [%1], 16, %2;"
                 :: "r"(dst), "l"(src), "r"(ssz) : "memory");
}
__device__ __forceinline__ void cp_commit() {
    asm volatile("cp.async.commit_group;" ::: "memory");
}
template<int Np>
__device__ __forceinline__ void cp_wait() {
    asm volatile("cp.async.wait_group %0;" :: "n"(Np) : "memory");
}
__device__ __forceinline__ void split1(float x, bf16& h, bf16& l) {
    h = __float2bfloat16_rn(x);
    l = __float2bfloat16_rn(x - __bfloat162float(h));
}

// ---------------- weight hi/lo split ----------------
__global__ void wsplit_kernel(const float* __restrict__ w, bf16* __restrict__ wh,
                              bf16* __restrict__ wl, int n4) {
    int i = blockIdx.x * blockDim.x + threadIdx.x;
    if (i >= n4) return;
    float4 v = reinterpret_cast<const float4*>(w)[i];
    bf16 h0, h1, h2, h3, l0, l1, l2, l3;
    split1(v.x, h0, l0); split1(v.y, h1, l1);
    split1(v.z, h2, l2); split1(v.w, h3, l3);
    __nv_bfloat162 hp0; hp0.x = h0; hp0.y = h1;
    __nv_bfloat162 hp1; hp1.x = h2; hp1.y = h3;
    __nv_bfloat162 lp0; lp0.x = l0; lp0.y = l1;
    __nv_bfloat162 lp1; lp1.x = l2; lp1.y = l3;
    uint2 hh = make_uint2(*reinterpret_cast<uint32_t*>(&hp0), *reinterpret_cast<uint32_t*>(&hp1));
    uint2 ll = make_uint2(*reinterpret_cast<uint32_t*>(&lp0), *reinterpret_cast<uint32_t*>(&lp1));
    reinterpret_cast<uint2*>(wh)[i] = hh;
    reinterpret_cast<uint2*>(wl)[i] = ll;
}

// ---------------- LayerNorm -> bf16 hi/lo planes ----------------
__global__ void ln_hl_kernel(const float* __restrict__ in, const float* __restrict__ w,
                             const float* __restrict__ b,
                             bf16* __restrict__ oh, bf16* __restrict__ ol) {
    int row = blockIdx.x;
    int tid = threadIdx.x;
    const float* x = in + (long)row * DMODEL;
    float v[3], s = 0.f, ss = 0.f;
    #pragma unroll
    for (int i = 0; i < 3; i++) {
        v[i] = x[tid + i * 256];
        s += v[i]; ss += v[i] * v[i];
    }
    __shared__ float sr[8], sr2[8], bres[2];
    float ws = warp_sum(s), ws2 = warp_sum(ss);
    int lane = tid & 31, wid = tid >> 5;
    if (lane == 0) { sr[wid] = ws; sr2[wid] = ws2; }
    __syncthreads();
    if (tid == 0) {
        float a = 0.f, c = 0.f;
        #pragma unroll
        for (int i = 0; i < 8; i++) { a += sr[i]; c += sr2[i]; }
        bres[0] = a; bres[1] = c;
    }
    __syncthreads();
    float mu  = bres[0] * (1.f / DMODEL);
    float var = bres[1] * (1.f / DMODEL) - mu * mu;
    float r = rsqrtf(var + EPSV);
    #pragma unroll
    for (int i = 0; i < 3; i++) {
        int c = tid + i * 256;
        float o = (v[i] - mu) * r * w[c] + b[c];
        bf16 h, l; split1(o, h, l);
        oh[(long)row * DMODEL + c] = h;
        ol[(long)row * DMODEL + c] = l;
    }
}

// ======= GEMM (pre-split bf16 hi/lo, cp.async x3, ldmatrix, HMMA 3-product) ==
#define RS 80
#define A_PL (128 * RS)
#define B_PL (64 * RS)
#define STG  (2 * A_PL + 2 * B_PL)
#define GEMM_SMEM (3 * STG)

template<int EPI, int OUTHL>
__global__ void __launch_bounds__(256, 2) gemm_bf16p(
        const bf16* __restrict__ Ah_, const bf16* __restrict__ Al_,
        const bf16* __restrict__ Wh_, const bf16* __restrict__ Wl_,
        const float* __restrict__ bias, const float* __restrict__ resid,
        float* __restrict__ C, bf16* __restrict__ Ch, bf16* __restrict__ Cl,
        int M, int N, int K) {
    extern __shared__ char smem[];
    uint32_t sb = smem_u32(smem);
    const int tid = threadIdx.x;
    const int lane = tid & 31, wid = tid >> 5;
    const int warpM = wid & 3, warpN = wid >> 2;
    const int row0 = blockIdx.y * 128;
    const int col0 = blockIdx.x * 64;
    const int quad = lane >> 3, r8 = lane & 7;
    const int g = lane >> 2, tg = lane & 3;

    float acc[2][4][4];
    #pragma unroll
    for (int mt = 0; mt < 2; mt++)
        #pragma unroll
        for (int nt = 0; nt < 4; nt++)
            #pragma unroll
            for (int i = 0; i < 4; i++) acc[mt][nt][i] = 0.f;

    const int ar0 = tid >> 2,          ac0 = tid & 3;
    const int ar1 = (tid + 256) >> 2,  ac1 = ac0;
    const int br  = tid >> 2,          bc  = tid & 3;
    const int bn  = col0 + br;
    const int bnc = bn < N ? bn : (N - 1);
    const uint32_t bsz = bn < N ? 16u : 0u;

    auto issue = [&](int kt, int st) {
        uint32_t base = sb + st * STG;
        int k0 = kt * 32;
        cpasync16(base + ar0 * RS + ac0 * 16,        &Ah_[(long)(row0 + ar0) * K + k0 + ac0 * 8], 16);
        cpasync16(base + A_PL + ar0 * RS + ac0 * 16, &Al_[(long)(row0 + ar0) * K + k0 + ac0 * 8], 16);
        cpasync16(base + ar1 * RS + ac1 * 16,        &Ah_[(long)(row0 + ar1) * K + k0 + ac1 * 8], 16);
        cpasync16(base + A_PL + ar1 * RS + ac1 * 16, &Al_[(long)(row0 + ar1) * K + k0 + ac1 * 8], 16);
        cpasync16(base + 2 * A_PL + br * RS + bc * 16,        &Wh_[(long)bnc * K + k0 + bc * 8], bsz);
        cpasync16(base + 2 * A_PL + B_PL + br * RS + bc * 16, &Wl_[(long)bnc * K + k0 + bc * 8], bsz);
        cp_commit();
    };

    const int ntiles = K / 32;
    issue(0, 0);
    issue(1, 1);

    for (int kt = 0; kt < ntiles; kt++) {
        cp_wait<1>();
        __syncthreads();
        if (kt + 2 < ntiles) issue(kt + 2, (kt + 2) % 3);
        else cp_commit();

        uint32_t base = sb + (kt % 3) * STG;
        uint32_t pAh = base, pAl = base + A_PL;
        uint32_t pBh = base + 2 * A_PL, pBl = pBh + B_PL;

        uint32_t ah[2][2][4], al[2][2][4], bh[2][2][4], bl[2][2][4];
        {
            uint32_t kbA = (quad >> 1) * 16;
            uint32_t kbB = (quad & 1) * 16;
            #pragma unroll
            for (int mt = 0; mt < 2; mt++) {
                uint32_t ra = (uint32_t)((warpM * 32 + mt * 16 + (quad & 1) * 8 + r8) * RS) + kbA;
                ldsm4(ah[0][mt], pAh + ra);
                ldsm4(al[0][mt], pAl + ra);
            }
            #pragma unroll
            for (int nt = 0; nt < 2; nt++) {
                uint32_t rb = (uint32_t)((warpN * 32 + nt * 16 + (quad >> 1) * 8 + r8) * RS) + kbB;
                ldsm4(bh[0][nt], pBh + rb);
                ldsm4(bl[0][nt], pBl + rb);
            }
        }
        #pragma unroll
        for (int slab = 0; slab < 2; slab++) {
            if (slab == 0) {
                uint32_t kbA = 32 + (quad >> 1) * 16;
                uint32_t kbB = 32 + (quad & 1) * 16;
                #pragma unroll
                for (int mt = 0; mt < 2; mt++) {
                    uint32_t ra = (uint32_t)((warpM * 32 + mt * 16 + (quad & 1) * 8 + r8) * RS) + kbA;
                    ldsm4(ah[1][mt], pAh + ra);
                    ldsm4(al[1][mt], pAl + ra);
                }
                #pragma unroll
                for (int nt = 0; nt < 2; nt++) {
                    uint32_t rb = (uint32_t)((warpN * 32 + nt * 16 + (quad >> 1) * 8 + r8) * RS) + kbB;
                    ldsm4(bh[1][nt], pBh + rb);
                    ldsm4(bl[1][nt], pBl + rb);
                }
            }
            #pragma unroll
            for (int mt = 0; mt < 2; mt++)
                #pragma unroll
                for (int nt16 = 0; nt16 < 2; nt16++) {
                    mma_bf16(acc[mt][nt16 * 2 + 0], ah[slab][mt], &bl[slab][nt16][0]);
                    mma_bf16(acc[mt][nt16 * 2 + 0], al[slab][mt], &bh[slab][nt16][0]);
                    mma_bf16(acc[mt][nt16 * 2 + 0], ah[slab][mt], &bh[slab][nt16][0]);
                    mma_bf16(acc[mt][nt16 * 2 + 1], ah[slab][mt], &bl[slab][nt16][2]);
                    mma_bf16(acc[mt][nt16 * 2 + 1], al[slab][mt], &bh[slab][nt16][2]);
                    mma_bf16(acc[mt][nt16 * 2 + 1], ah[slab][mt], &bh[slab][nt16][2]);
                }
        }
    }

    #pragma unroll
    for (int mt = 0; mt < 2; mt++) {
        int rbase = row0 + warpM * 32 + mt * 16 + g;
        #pragma unroll
        for (int nt = 0; nt < 4; nt++) {
            int col = col0 + warpN * 32 + nt * 8 + tg * 2;
            if (col < N) {
                float2 v0 = make_float2(acc[mt][nt][0], acc[mt][nt][1]);
                float2 v1 = make_float2(acc[mt][nt][2], acc[mt][nt][3]);
                if (EPI == 1) {
                    float b0 = bias[col], b1 = bias[col + 1];
                    v0.x = geluf(v0.x + b0); v0.y = geluf(v0.y + b1);
                    v1.x = geluf(v1.x + b0); v1.y = geluf(v1.y + b1);
                }
                if (EPI == 2) {
                    float b0 = bias[col], b1 = bias[col + 1];
                    float2 r0 = *reinterpret_cast<const float2*>(&resid[(long)rbase * N + col]);
                    float2 r1 = *reinterpret_cast<const float2*>(&resid[(long)(rbase + 8) * N + col]);
                    v0.x += b0 + r0.x; v0.y += b1 + r0.y;
                    v1.x += b0 + r1.x; v1.y += b1 + r1.y;
                }
                if (OUTHL) {
                    bf16 h0, h1, l0, l1;
                    split1(v0.x, h0, l0); split1(v0.y, h1, l1);
                    __nv_bfloat162 hp; hp.x = h0; hp.y = h1;
                    __nv_bfloat162 lp; lp.x = l0; lp.y = l1;
                    *reinterpret_cast<uint32_t*>(&Ch[(long)rbase * N + col]) = *reinterpret_cast<uint32_t*>(&hp);
                    *reinterpret_cast<uint32_t*>(&Cl[(long)rbase * N + col]) = *reinterpret_cast<uint32_t*>(&lp);
                    split1(v1.x, h0, l0); split1(v1.y, h1, l1);
                    hp.x = h0; hp.y = h1; lp.x = l0; lp.y = l1;
                    *reinterpret_cast<uint32_t*>(&Ch[(long)(rbase + 8) * N + col]) = *reinterpret_cast<uint32_t*>(&hp);
                    *reinterpret_cast<uint32_t*>(&Cl[(long)(rbase + 8) * N + col]) = *reinterpret_cast<uint32_t*>(&lp);
                } else {
                    *reinterpret_cast<float2*>(&C[(long)rbase * N + col])       = v0;
                    *reinterpret_cast<float2*>(&C[(long)(rbase + 8) * N + col]) = v1;
                }
            }
        }
    }
}

// ---------------- depthwise conv (causal fwd + anti-causal bwd) + SiLU --------
__global__ void conv_kernel(const float* __restrict__ zx, const float* __restrict__ cw,
                            const float* __restrict__ cb,
                            float* __restrict__ xf, float* __restrict__ xb) {
    long idx = (long)blockIdx.x * blockDim.x + threadIdx.x;
    if (idx >= (long)BT * CONVDIM) return;
    int c = (int)(idx % CONVDIM);
    long bt = idx / CONVDIM;
    int t = (int)(bt % SEQn);
    int b = (int)(bt / SEQn);
    float w0 = cw[c*4+0], w1 = cw[c*4+1], w2 = cw[c*4+2], w3 = cw[c*4+3];
    float bias = cb[c];
    const float* base = zx + ((long)b * SEQn) * DIP + DINNER + c;
    float af = bias;
    if (t >= 3) af += w0 * base[(long)(t-3) * DIP];
    if (t >= 2) af += w1 * base[(long)(t-2) * DIP];
    if (t >= 1) af += w2 * base[(long)(t-1) * DIP];
    af += w3 * base[(long)t * DIP];
    xf[idx] = siluf(af);
    float ab = bias;
    if (t + 3 < SEQn) ab += w0 * base[(long)(t+3) * DIP];
    if (t + 2 < SEQn) ab += w1 * base[(long)(t+2) * DIP];
    if (t + 1 < SEQn) ab += w2 * base[(long)(t+1) * DIP];
    ab += w3 * base[(long)t * DIP];
    xb[idx] = siluf(ab);
}

// ---------------- dt processing ----------------
__global__ void dt_kernel(const float* __restrict__ zx, const float* __restrict__ dt_bias,
                          const float* __restrict__ A_log,
                          float* __restrict__ dtp, float* __restrict__ dAe) {
    int idx = blockIdx.x * blockDim.x + threadIdx.x;
    if (idx >= BT * NHEADSn) return;
    int h = idx % NHEADSn;
    long row = idx / NHEADSn;
    float d = zx[row * DIP + DINNER + CONVDIM + h] + dt_bias[h];
    float sp = (d > 20.f) ? d : log1pf(expf(d));
    dtp[idx] = sp;
    dAe[idx] = expf(-expf(A_log[h]) * sp);
}

// --------- apre: within-chunk prefix products of dA (scan order) -------------
__global__ void apre_kernel(const float* __restrict__ dAe, float* __restrict__ apre) {
    int gid = blockIdx.x * blockDim.x + threadIdx.x;
    if (gid >= NG96 * NCH) return;
    int c = gid % NCH;
    int r96 = gid / NCH;
    int hh = r96 % NHEADSn;
    int rb = r96 / NHEADSn;
    int b = rb % BSZn, dir = rb / BSZn;
    float a = 1.f;
    for (int sl = 0; sl < CHS; sl++) {
        int s = c * CHS + sl;
        int t = dir ? (SEQn - 1 - s) : s;
        a *= dAe[((long)b * SEQn + t) * NHEADSn + hh];
        apre[(long)r96 * SEQn + s] = a;
    }
}

// --------- chunked local scan: smem-staged, 768 blocks -----------------------
// dynamic smem: sB[4096] sC[4096] sX[4096] sY[4096] sdt[64] sdA[64]
#define SCAN_SMEM ((4 * 4096 + 128) * 4)
__global__ void __launch_bounds__(256) chunk_scan(
        const float* __restrict__ xbcf, const float* __restrict__ xbcb,
        const float* __restrict__ dtp, const float* __restrict__ dAe,
        const float* __restrict__ Dp_,
        float* __restrict__ yf, float* __restrict__ yb,
        float* __restrict__ hend) {
    extern __shared__ float sm[];
    float* sB = sm;
    float* sC = sm + 4096;
    float* sX = sm + 8192;
    float* sY = sm + 12288;
    float* sdt = sm + 16384;
    float* sdA = sm + 16448;

    int blk = blockIdx.x;
    int c = blk % NCH;
    int r96 = blk / NCH;
    int hh = r96 % NHEADSn;
    int rb = r96 / NHEADSn;
    int b = rb % BSZn, dir = rb / BSZn;
    const float* xbc = dir ? xbcb : xbcf;
    float* y = dir ? yb : yf;
    int tid = threadIdx.x;
    int p = tid >> 2, q = tid & 3;
    long rowbase = (long)b * SEQn;
    int s0 = c * CHS;

    // stage chunk into smem (coalesced float4)
    #pragma unroll
    for (int i = 0; i < 4; i++) {
        int idx4 = tid + i * 256;          // 0..1023
        int sl = idx4 >> 4;                // local step
        int ch4 = idx4 & 15;               // float4 within 64 floats
        int s = s0 + sl;
        int t = dir ? (SEQn - 1 - s) : s;
        const float* base = xbc + (rowbase + t) * CONVDIM;
        reinterpret_cast<float4*>(sB)[idx4] = *reinterpret_cast<const float4*>(base + DINNER + ch4 * 4);
        reinterpret_cast<float4*>(sC)[idx4] = *reinterpret_cast<const float4*>(base + DINNER + DSTATEn + ch4 * 4);
        reinterpret_cast<float4*>(sX)[idx4] = *reinterpret_cast<const float4*>(base + hh * HEADDIMn + ch4 * 4);
    }
    if (tid < CHS) {
        int s = s0 + tid;
        int t = dir ? (SEQn - 1 - s) : s;
        long row = rowbase + t;
        sdt[tid] = dtp[row * NHEADSn + hh];
        sdA[tid] = dAe[row * NHEADSn + hh];
    }
    __syncthreads();

    float Dv = Dp_[hh];
    float hst[16];
    #pragma unroll
    for (int j = 0; j < 16; j++) hst[j] = 0.f;

    for (int i = 0; i < CHS; i++) {
        float cdt = sdt[i], cdA = sdA[i];
        float cx = sX[i * 64 + p];
        float bv[16], cv[16];
        const float4* pb = reinterpret_cast<const float4*>(&sB[i * 64 + q * 16]);
        const float4* pc = reinterpret_cast<const float4*>(&sC[i * 64 + q * 16]);
        *reinterpret_cast<float4*>(&bv[0])  = pb[0];
        *reinterpret_cast<float4*>(&bv[4])  = pb[1];
        *reinterpret_cast<float4*>(&bv[8])  = pb[2];
        *reinterpret_cast<float4*>(&bv[12]) = pb[3];
        *reinterpret_cast<float4*>(&cv[0])  = pc[0];
        *reinterpret_cast<float4*>(&cv[4])  = pc[1];
        *reinterpret_cast<float4*>(&cv[8])  = pc[2];
        *reinterpret_cast<float4*>(&cv[12]) = pc[3];
        float c1 = cdt * cx;
        float yv0 = (q == 0) ? Dv * cx : 0.f;
        float yv1 = 0.f, yv2 = 0.f, yv3 = 0.f;
        #pragma unroll
        for (int j = 0; j < 16; j += 4) {
            hst[j]     = cdA * hst[j]     + c1 * bv[j];     yv0 += hst[j]     * cv[j];
            hst[j + 1] = cdA * hst[j + 1] + c1 * bv[j + 1]; yv1 += hst[j + 1] * cv[j + 1];
            hst[j + 2] = cdA * hst[j + 2] + c1 * bv[j + 2]; yv2 += hst[j + 2] * cv[j + 2];
            hst[j + 3] = cdA * hst[j + 3] + c1 * bv[j + 3]; yv3 += hst[j + 3] * cv[j + 3];
        }
        float yv = (yv0 + yv1) + (yv2 + yv3);
        yv += __shfl_xor_sync(0xffffffffu, yv, 1);
        yv += __shfl_xor_sync(0xffffffffu, yv, 2);
        if (q == 0) sY[i * 64 + p] = yv;
    }
    __syncthreads();
    // coalesced y writeback
    #pragma unroll
    for (int i = 0; i < 4; i++) {
        int idx4 = tid + i * 256;
        int sl = idx4 >> 4;
        int ch4 = idx4 & 15;
        int s = s0 + sl;
        int t = dir ? (SEQn - 1 - s) : s;
        *reinterpret_cast<float4*>(&y[(rowbase + t) * DINNER + hh * HEADDIMn + ch4 * 4]) =
            reinterpret_cast<float4*>(sY)[idx4];
    }
    // write local chunk-end state
    float4* he = reinterpret_cast<float4*>(&hend[(long)blk * 4096 + p * 64 + q * 16]);
    he[0] = *reinterpret_cast<float4*>(&hst[0]);
    he[1] = *reinterpret_cast<float4*>(&hst[4]);
    he[2] = *reinterpret_cast<float4*>(&hst[8]);
    he[3] = *reinterpret_cast<float4*>(&hst[12]);
}

// --------- combine: H_{c+1} = P_c * H_c + hend_c ; store carries -------------
__global__ void combine_kernel(const float* __restrict__ hend, const float* __restrict__ apre,
                               float* __restrict__ Hc) {
    int r96 = blockIdx.x;
    int tid = threadIdx.x;
    int p = tid >> 2, q = tid & 3;
    int eo = p * 64 + q * 16;
    float H[16];
    #pragma unroll
    for (int j = 0; j < 16; j++) H[j] = 0.f;
    for (int c = 0; c < NCH; c++) {
        if (c > 0) {
            float4* dst = reinterpret_cast<float4*>(&Hc[((long)r96 * NCH + c) * 4096 + eo]);
            dst[0] = *reinterpret_cast<float4*>(&H[0]);
            dst[1] = *reinterpret_cast<float4*>(&H[4]);
            dst[2] = *reinterpret_cast<float4*>(&H[8]);
            dst[3] = *reinterpret_cast<float4*>(&H[12]);
        }
        float Pc = apre[(long)r96 * SEQn + c * CHS + CHS - 1];
        const float4* he = reinterpret_cast<const float4*>(&hend[((long)r96 * NCH + c) * 4096 + eo]);
        float hv[16];
        *reinterpret_cast<float4*>(&hv[0])  = he[0];
        *reinterpret_cast<float4*>(&hv[4])  = he[1];
        *reinterpret_cast<float4*>(&hv[8])  = he[2];
        *reinterpret_cast<float4*>(&hv[12]) = he[3];
        #pragma unroll
        for (int j = 0; j < 16; j++) H[j] = Pc * H[j] + hv[j];
    }
}

// --------- correction: y[s] += a_s * (C_s · H_c), smem-staged ----------------
__global__ void __launch_bounds__(256) corr_kernel(
        const float* __restrict__ xbcf, const float* __restrict__ xbcb,
        const float* __restrict__ apre, const float* __restrict__ Hc,
        float* __restrict__ yf, float* __restrict__ yb) {
    __shared__ float sC2[4096], sY2[4096], sa[CHS];
    int blk = blockIdx.x;                  // r96*(NCH-1) + (c-1)
    int c = blk % (NCH - 1) + 1;
    int r96 = blk / (NCH - 1);
    int hh = r96 % NHEADSn;
    int rb = r96 / NHEADSn;
    int b = rb % BSZn, dir = rb / BSZn;
    const float* xbc = dir ? xbcb : xbcf;
    float* y = dir ? yb : yf;
    int tid = threadIdx.x;
    int p = tid >> 2, q = tid & 3;
    long rowbase = (long)b * SEQn;
    int s0 = c * CHS;

    #pragma unroll
    for (int i = 0; i < 4; i++) {
        int idx4 = tid + i * 256;
        int sl = idx4 >> 4;
        int ch4 = idx4 & 15;
        int s = s0 + sl;
        int t = dir ? (SEQn - 1 - s) : s;
        reinterpret_cast<float4*>(sC2)[idx4] = *reinterpret_cast<const float4*>(
            &xbc[(rowbase + t) * CONVDIM + DINNER + DSTATEn + ch4 * 4]);
    }
    if (tid < CHS) sa[tid] = apre[(long)r96 * SEQn + s0 + tid];
    __syncthreads();

    float H[16];
    const float4* hp = reinterpret_cast<const float4*>(&Hc[((long)r96 * NCH + c) * 4096 + p * 64 + q * 16]);
    *reinterpret_cast<float4*>(&H[0])  = hp[0];
    *reinterpret_cast<float4*>(&H[4])  = hp[1];
    *reinterpret_cast<float4*>(&H[8])  = hp[2];
    *reinterpret_cast<float4*>(&H[12]) = hp[3];

    for (int sl = 0; sl < CHS; sl++) {
        float cvv[16];
        const float4* pc = reinterpret_cast<const float4*>(&sC2[sl * 64 + q * 16]);
        *reinterpret_cast<float4*>(&cvv[0])  = pc[0];
        *reinterpret_cast<float4*>(&cvv[4])  = pc[1];
        *reinterpret_cast<float4*>(&cvv[8])  = pc[2];
        *reinterpret_cast<float4*>(&cvv[12]) = pc[3];
        float t0 = 0.f, t1 = 0.f, t2 = 0.f, t3 = 0.f;
        #pragma unroll
        for (int j = 0; j < 16; j += 4) {
            t0 += H[j]     * cvv[j];
            t1 += H[j + 1] * cvv[j + 1];
            t2 += H[j + 2] * cvv[j + 2];
            t3 += H[j + 3] * cvv[j + 3];
        }
        float tot = (t0 + t1) + (t2 + t3);
        tot += __shfl_xor_sync(0xffffffffu, tot, 1);
        tot += __shfl_xor_sync(0xffffffffu, tot, 2);
        if (q == 0) sY2[sl * 64 + p] = sa[sl] * tot;
    }
    __syncthreads();
    #pragma unroll
    for (int i = 0; i < 4; i++) {
        int idx4 = tid + i * 256;
        int sl = idx4 >> 4;
        int ch4 = idx4 & 15;
        int s = s0 + sl;
        int t = dir ? (SEQn - 1 - s) : s;
        float* dst = &y[(rowbase + t) * DINNER + hh * HEADDIMn + ch4 * 4];
        float4 old = *reinterpret_cast<float4*>(dst);
        float4 add = reinterpret_cast<float4*>(sY2)[idx4];
        old.x += add.x; old.y += add.y; old.z += add.z; old.w += add.w;
        *reinterpret_cast<float4*>(dst) = old;
    }
}

// ------ gate + RMSNorm + sum -> bf16 hi/lo planes ----------------
__global__ void gatenorm_kernel(const float* __restrict__ yf, const float* __restrict__ yb,
                                const float* __restrict__ zx, const float* __restrict__ nw,
                                bf16* __restrict__ oh, bf16* __restrict__ ol) {
    int row = blockIdx.x;
    int tid = threadIdx.x;
    const float* z = zx + (long)row * DIP;
    float gf[6], gb[6], ssf = 0.f, ssb = 0.f;
    #pragma unroll
    for (int i = 0; i < 6; i++) {
        int c = tid + i * 256;
        float s = siluf(z[c]);
        float a = yf[(long)row * DINNER + c] * s;
        float d = yb[(long)row * DINNER + c] * s;
        gf[i] = a; gb[i] = d;
        ssf += a * a; ssb += d * d;
    }
    __shared__ float r1[8], r2[8], bres[2];
    float w1 = warp_sum(ssf), w2 = warp_sum(ssb);
    int lane = tid & 31, wid = tid >> 5;
    if (lane == 0) { r1[wid] = w1; r2[wid] = w2; }
    __syncthreads();
    if (tid == 0) {
        float a = 0.f, c = 0.f;
        #pragma unroll
        for (int i = 0; i < 8; i++) { a += r1[i]; c += r2[i]; }
        bres[0] = a; bres[1] = c;
    }
    __syncthreads();
    float rf = rsqrtf(bres[0] * (1.f / DINNER) + EPSV);
    float rb = rsqrtf(bres[1] * (1.f / DINNER) + EPSV);
    #pragma unroll
    for (int i = 0; i < 6; i++) {
        int c = tid + i * 256;
        float o = (gf[i] * rf + gb[i] * rb) * nw[c];
        bf16 h, l; split1(o, h, l);
        oh[(long)row * DINNER + c] = h;
        ol[(long)row * DINNER + c] = l;
    }
}

// ---------------- launch ----------------
extern "C" void kernel_launch(void* const* d_in, const int* in_sizes, int n_in,
                              void* d_out, int out_size) {
    const float* x        = (const float*)d_in[0];
    const float* in_proj  = (const float*)d_in[1];
    const float* conv_w   = (const float*)d_in[2];
    const float* conv_b   = (const float*)d_in[3];
    const float* dt_bias  = (const float*)d_in[4];
    const float* A_log    = (const float*)d_in[5];
    const float* D_param  = (const float*)d_in[6];
    const float* norm_w   = (const float*)d_in[7];
    const float* out_proj = (const float*)d_in[8];
    const float* ln1_w    = (const float*)d_in[9];
    const float* ln1_b    = (const float*)d_in[10];
    const float* ln2_w    = (const float*)d_in[11];
    const float* ln2_b    = (const float*)d_in[12];
    const float* ff_w1    = (const float*)d_in[13];
    const float* ff_b1    = (const float*)d_in[14];
    const float* ff_w2    = (const float*)d_in[15];
    const float* ff_b2    = (const float*)d_in[16];
    float* out = (float*)d_out;

    float *p_zx, *p_xbcf, *p_xbcb, *p_dtp, *p_dAe, *p_yf, *p_yb, *p_mi;
    float *p_apre, *p_hend, *p_Hc;
    bf16 *p_xnh, *p_xnl, *p_ysh, *p_ysl, *p_mh, *p_ml, *p_h1h, *p_h1l;
    bf16 *p_wip_h, *p_wip_l, *p_wop_h, *p_wop_l, *p_w1_h, *p_w1_l, *p_w2_h, *p_w2_l;
    cudaGetSymbolAddress((void**)&p_zx,   g_zx);
    cudaGetSymbolAddress((void**)&p_xbcf, g_xbcf);
    cudaGetSymbolAddress((void**)&p_xbcb, g_xbcb);
    cudaGetSymbolAddress((void**)&p_dtp,  g_dtp);
    cudaGetSymbolAddress((void**)&p_dAe,  g_dAe);
    cudaGetSymbolAddress((void**)&p_yf,   g_yf);
    cudaGetSymbolAddress((void**)&p_yb,   g_yb);
    cudaGetSymbolAddress((void**)&p_mi,   g_mi);
    cudaGetSymbolAddress((void**)&p_apre, g_apre);
    cudaGetSymbolAddress((void**)&p_hend, g_hend);
    cudaGetSymbolAddress((void**)&p_Hc,   g_Hc);
    cudaGetSymbolAddress((void**)&p_xnh,  g_xnh);
    cudaGetSymbolAddress((void**)&p_xnl,  g_xnl);
    cudaGetSymbolAddress((void**)&p_ysh,  g_ysh);
    cudaGetSymbolAddress((void**)&p_ysl,  g_ysl);
    cudaGetSymbolAddress((void**)&p_mh,   g_mh);
    cudaGetSymbolAddress((void**)&p_ml,   g_ml);
    cudaGetSymbolAddress((void**)&p_h1h,  g_h1h);
    cudaGetSymbolAddress((void**)&p_h1l,  g_h1l);
    cudaGetSymbolAddress((void**)&p_wip_h, g_wip_h);
    cudaGetSymbolAddress((void**)&p_wip_l, g_wip_l);
    cudaGetSymbolAddress((void**)&p_wop_h, g_wop_h);
    cudaGetSymbolAddress((void**)&p_wop_l, g_wop_l);
    cudaGetSymbolAddress((void**)&p_w1_h,  g_w1_h);
    cudaGetSymbolAddress((void**)&p_w1_l,  g_w1_l);
    cudaGetSymbolAddress((void**)&p_w2_h,  g_w2_h);
    cudaGetSymbolAddress((void**)&p_w2_l,  g_w2_l);

    cudaFuncSetAttribute(gemm_bf16p<0,0>, cudaFuncAttributeMaxDynamicSharedMemorySize, GEMM_SMEM);
    cudaFuncSetAttribute(gemm_bf16p<1,1>, cudaFuncAttributeMaxDynamicSharedMemorySize, GEMM_SMEM);
    cudaFuncSetAttribute(gemm_bf16p<2,0>, cudaFuncAttributeMaxDynamicSharedMemorySize, GEMM_SMEM);
    cudaFuncSetAttribute(chunk_scan, cudaFuncAttributeMaxDynamicSharedMemorySize, SCAN_SMEM);

    // #0 ln1(x) -> xn planes
    ln_hl_kernel<<<BT, 256>>>(x, ln1_w, ln1_b, p_xnh, p_xnl);
    // #1 split in_proj
    wsplit_kernel<<<(DIP*DMODEL/4 + 255) / 256, 256>>>(in_proj,  p_wip_h, p_wip_l, DIP*DMODEL/4);
    // #2 zxbcdt = xn @ in_proj^T
    gemm_bf16p<0,0><<<dim3((DIP + 63) / 64, BT / 128), 256, GEMM_SMEM>>>(
        p_xnh, p_xnl, p_wip_h, p_wip_l, nullptr, nullptr, p_zx, nullptr, nullptr, BT, DIP, DMODEL);
    // #3 conv + silu (both directions)   <-- ncu capture slot
    {
        long tot = (long)BT * CONVDIM;
        conv_kernel<<<(int)((tot + 255) / 256), 256>>>(p_zx, conv_w, conv_b, p_xbcf, p_xbcb);
    }
    // #4 dt processing
    dt_kernel<<<(BT * NHEADSn + 255) / 256, 256>>>(p_zx, dt_bias, A_log, p_dtp, p_dAe);
    // #5 prefix products
    apre_kernel<<<(NG96 * NCH + 255) / 256, 256>>>(p_dAe, p_apre);
    // #6 chunked local scans (smem-staged)
    chunk_scan<<<NG96 * NCH, 256, SCAN_SMEM>>>(p_xbcf, p_xbcb, p_dtp, p_dAe, D_param, p_yf, p_yb, p_hend);
    // #7 combine carries
    combine_kernel<<<NG96, 256>>>(p_hend, p_apre, p_Hc);
    // #8 correction (smem-staged)
    corr_kernel<<<NG96 * (NCH - 1), 256>>>(p_xbcf, p_xbcb, p_apre, p_Hc, p_yf, p_yb);
    // #9 gate + RMSNorm + sum -> ysum planes
    gatenorm_kernel<<<BT, 256>>>(p_yf, p_yb, p_zx, norm_w, p_ysh, p_ysl);
    // #10 split out_proj
    wsplit_kernel<<<(DMODEL*DINNER/4 + 255) / 256, 256>>>(out_proj, p_wop_h, p_wop_l, DMODEL*DINNER/4);
    // #11 mi = ysum @ out_proj^T
    gemm_bf16p<0,0><<<dim3(DMODEL / 64, BT / 128), 256, GEMM_SMEM>>>(
        p_ysh, p_ysl, p_wop_h, p_wop_l, nullptr, nullptr, p_mi, nullptr, nullptr, BT, DMODEL, DINNER);
    // #12 ln2 -> m planes
    ln_hl_kernel<<<BT, 256>>>(p_mi, ln2_w, ln2_b, p_mh, p_ml);
    // #13 split ff_w1
    wsplit_kernel<<<(DFF*DMODEL/4 + 255) / 256, 256>>>(ff_w1, p_w1_h, p_w1_l, DFF*DMODEL/4);
    // #14 h1 = gelu(m @ ff_w1^T + b1)
    gemm_bf16p<1,1><<<dim3(DFF / 64, BT / 128), 256, GEMM_SMEM>>>(
        p_mh, p_ml, p_w1_h, p_w1_l, ff_b1, nullptr, nullptr, p_h1h, p_h1l, BT, DFF, DMODEL);
    // #15 split ff_w2
    wsplit_kernel<<<(DMODEL*DFF/4 + 255) / 256, 256>>>(ff_w2, p_w2_h, p_w2_l, DMODEL*DFF/4);
    // #16 out = h1 @ ff_w2^T + b2 + x
    gemm_bf16p<2,0><<<dim3(DMODEL / 64, BT / 128), 256, GEMM_SMEM>>>(
        p_h1h, p_h1l, p_w2_h, p_w2_l, ff_b2, x, out, nullptr, nullptr, BT, DMODEL, DFF);
}